// round 16
// baseline (speedup 1.0000x reference)
#include <cuda_runtime.h>
#include <cstdint>

// out[b,t] = sum_w <x1[b,:,(t+w+450)%900,:], x2[b,:,w,:]>
// Spectral: per channel, circular cross-correlation via one packed FFT-900.
//   z = x1 + i*x2;  X1 = (Z(k)+conj(Z(-k)))/2,  X2 = (Z(k)-conj(Z(-k)))/(2i)
//   S[k] = sum_ch (-1)^k X1(k) conj(X2(k)),  out[t] = (1/900) Re sum_k S[k] e^{+2pi i k t/900}
// FFT-900 = 30x30 CT, DFT-30 = 5x6 CT (hardcoded W5/W6 -> FFMA-imm).
// R16: R13's proven fft compute shape (no reg cap, smem cross-spectrum,
// 97.7KB smem, 1 CTA/SM) + direct sectored loads (no transpose kernel)
// + parallel spectrum-reduce + parallel iDFT.

#define W_ 900
#define B_ 16

__device__ float2 g_W900[W_];             // e^{-2 pi i j / 900}
__device__ float2 g_spart[2048 * 452];    // per-(b,chgroup) partial spectra
__device__ float2 g_S[B_ * 452];          // reduced spectra per batch

// smem layout (float2 units): zw 8*962 | W 904 | Pall 8*452
#define ZW_STRIDE 962
#define WSH_OFF   7696
#define PALL_OFF  8600
#define SMEM_F2   12216
#define SMEM_BYTES (SMEM_F2 * 8)          // 97728

// ---------------- small-DFT constants (e^{-2 pi i j / N}) ----------------
__device__ constexpr float W6re[6] = { 1.f,  0.5f, -0.5f, -1.f, -0.5f,  0.5f };
__device__ constexpr float W6im[6] = { 0.f, -0.86602540378f, -0.86602540378f, 0.f,
                                       0.86602540378f,  0.86602540378f };
__device__ constexpr float W5re[5] = { 1.f,  0.30901699437f, -0.80901699437f,
                                      -0.80901699437f,  0.30901699437f };
__device__ constexpr float W5im[5] = { 0.f, -0.95105651630f, -0.58778525229f,
                                       0.58778525229f,  0.95105651630f };

__device__ __forceinline__ float2 cmul(float2 a, float2 b) {
    return make_float2(a.x * b.x - a.y * b.y, a.x * b.y + a.y * b.x);
}

// DFT-30 (natural in/out), 30 = 5 x 6. MODE 0: row pass + W900^{lane*q},
// swizzled row store. MODE 1: column pass, final Z layout.
template <int MODE>
__device__ __forceinline__ void dft30_io(float2* v, float2* zw,
                                         const float2* Wsh, int lane) {
#pragma unroll
    for (int m1 = 0; m1 < 5; ++m1) {
        float2 e[6];
#pragma unroll
        for (int m2 = 0; m2 < 6; ++m2) e[m2] = v[m1 + 5 * m2];
#pragma unroll
        for (int q2 = 0; q2 < 6; ++q2) {
            float re = 0.f, im = 0.f;
#pragma unroll
            for (int m2 = 0; m2 < 6; ++m2) {
                const float wr = W6re[(m2 * q2) % 6];
                const float wi = W6im[(m2 * q2) % 6];
                re += e[m2].x * wr - e[m2].y * wi;
                im += e[m2].x * wi + e[m2].y * wr;
            }
            float2 t = make_float2(re, im);
            if (m1 * q2 != 0) t = cmul(t, Wsh[30 * m1 * q2]);  // W30^{m1 q2}
            v[m1 + 5 * q2] = t;
        }
    }
#pragma unroll
    for (int q2 = 0; q2 < 6; ++q2) {
        float2 f[5];
#pragma unroll
        for (int m1 = 0; m1 < 5; ++m1) f[m1] = v[m1 + 5 * q2];
#pragma unroll
        for (int q1 = 0; q1 < 5; ++q1) {
            float re = 0.f, im = 0.f;
#pragma unroll
            for (int m1 = 0; m1 < 5; ++m1) {
                const float wr = W5re[(m1 * q1) % 5];
                const float wi = W5im[(m1 * q1) % 5];
                re += f[m1].x * wr - f[m1].y * wi;
                im += f[m1].x * wi + f[m1].y * wr;
            }
            const int q = q2 + 6 * q1;
            float2 o = make_float2(re, im);
            if (MODE == 0) {
                o = cmul(o, Wsh[lane * q]);              // W900^{r q}
                zw[lane * 32 + ((q + lane) & 31)] = o;
            } else {
                zw[q * 32 + ((lane + q) & 31)] = o;
            }
        }
    }
}

// ---------------- kernel 0: twiddle table ----------------
__global__ void twiddle_kernel(int unused) {
    int j = blockIdx.x * 256 + threadIdx.x;
    if (j < W_) {
        double s, c;
        sincospi(-2.0 * (double)j / 900.0, &s, &c);
        g_W900[j] = make_float2((float)c, (float)s);
    }
}

// ---------------- kernel 1: FFT + cross-spectrum + CTA partial ----------
// grid 2048 = b*128 + (h*32 + cgrp); 8 warps, warp w owns channel c0 + w.
__global__ __launch_bounds__(256)
void fft_kernel(const float* __restrict__ x1, const float* __restrict__ x2) {
    extern __shared__ float2 sm[];
    float2* Wsh  = sm + WSH_OFF;
    float2* Pall = sm + PALL_OFF;

    const int tid  = threadIdx.x;
    const int lane = tid & 31;
    const int wid  = tid >> 5;
    const int bx   = blockIdx.x;
    const int b    = bx >> 7;
    const int sub  = bx & 127;
    const int h    = sub >> 5;
    const int c0   = (sub & 31) * 8;

    // twiddle table
    for (int j = tid; j < W_; j += 256) Wsh[j] = g_W900[j];

    // direct load: thread (w, c) reads both tensors, writes channel c's buffer
    {
        const float* s1 = x1 + ((size_t)(b * 4 + h) * W_) * 256 + c0;
        const float* s2 = x2 + ((size_t)(b * 4 + h) * W_) * 256 + c0;
        const int c = tid & 7;
        const int wo = tid >> 3;
#pragma unroll 4
        for (int it = 0; it < 29; ++it) {
            int w = it * 32 + wo;
            if (w < W_) {
                float v1 = s1[(size_t)w * 256 + c];
                float v2 = s2[(size_t)w * 256 + c];
                int r = w % 30, cc = w / 30;
                sm[c * ZW_STRIDE + r * 32 + ((cc + r) & 31)] = make_float2(v1, v2);
            }
        }
    }
    __syncthreads();

    float2* zw = sm + wid * ZW_STRIDE;
    float2* Pb = Pall + wid * 452;

    // stage 1: DFT-30 along rows + level-1 twiddle
    if (lane < 30) {
        float2 v[30];
#pragma unroll
        for (int c = 0; c < 30; ++c) v[c] = zw[lane * 32 + ((c + lane) & 31)];
        dft30_io<0>(v, zw, Wsh, lane);
    }
    __syncwarp();

    // stage 2: DFT-30 along columns
    if (lane < 30) {
        float2 v[30];
#pragma unroll
        for (int m = 0; m < 30; ++m) v[m] = zw[m * 32 + ((lane + m) & 31)];
        dft30_io<1>(v, zw, Wsh, lane);
    }
    __syncwarp();

    // combine: P[k] = (-1)^k X1(k) conj(X2(k)), k = 0..450 -> smem
    for (int k = lane; k <= 450; k += 32) {
        int m = (W_ - k) % W_;
        float2 A  = zw[(k / 30) * 32 + ((k % 30 + k / 30) & 31)];
        float2 Zm = zw[(m / 30) * 32 + ((m % 30 + m / 30) & 31)];
        float2 X1 = make_float2(0.5f * (A.x + Zm.x), 0.5f * (A.y - Zm.y));
        float2 D  = make_float2(0.5f * (A.x - Zm.x), 0.5f * (A.y + Zm.y));
        float pr = X1.x * D.y - X1.y * D.x;
        float pi = X1.x * D.x + X1.y * D.y;
        float sg = (k & 1) ? -1.f : 1.f;
        Pb[k] = make_float2(sg * pr, sg * pi);
    }
    __syncthreads();

    // CTA-reduce 8 warps -> partial spectrum for this (b, chgroup)
    float2* part = g_spart + (size_t)bx * 452;
    for (int k = tid; k <= 450; k += 256) {
        float2 s = make_float2(0.f, 0.f);
#pragma unroll
        for (int w = 0; w < 8; ++w) {
            float2 p = Pall[w * 452 + k];
            s.x += p.x; s.y += p.y;
        }
        part[k] = s;
    }
}

// ---------------- kernel 2: reduce 128 partials -> S[b][k] --------------
__global__ __launch_bounds__(256)
void reduce_spec_kernel(int unused) {
    const int idx = blockIdx.x * 256 + threadIdx.x;
    if (idx >= B_ * 451) return;
    const int b = idx / 451;
    const int k = idx - b * 451;
    float2 s = make_float2(0.f, 0.f);
#pragma unroll 8
    for (int g = 0; g < 128; ++g) {
        float2 p = g_spart[(size_t)(b * 128 + g) * 452 + k];
        s.x += p.x; s.y += p.y;
    }
    g_S[b * 452 + k] = s;
}

// ---------------- kernel 3: parallel inverse real DFT -------------------
// grid (16, 30); CTA: b, 30 t's; thread = (t_local, kgroup of 8).
__global__ __launch_bounds__(256)
void idft_kernel(float* __restrict__ out) {
    __shared__ float2 S[452];
    __shared__ float2 Wsh[W_];
    const int tid = threadIdx.x;
    const int b = blockIdx.x;

    for (int j = tid; j < W_; j += 256) Wsh[j] = g_W900[j];
    for (int k = tid; k <= 450; k += 256) S[k] = g_S[b * 452 + k];
    __syncthreads();

    const int tq = tid >> 3;            // 0..31 (valid outputs: < 30)
    const int kg = tid & 7;
    const int traw = blockIdx.y * 30 + tq;
    const int t = (tq < 30) ? traw : 0; // clamp dead lanes: keeps the
                                        // incremental index in [0, 900)
    const int k0 = kg * 57;
    const int k1 = (k0 + 56 < 450) ? (k0 + 56) : 450;

    float acc = 0.f;
    int idx = (k0 * t) % W_;
    for (int k = k0; k <= k1; ++k) {
        float2 W = Wsh[idx];
        float2 s = S[k];
        acc += s.x * W.x + s.y * W.y;   // Re(S e^{+i th}), W = e^{-i th}
        idx += t; if (idx >= W_) idx -= W_;
    }
    // reduce the 8 k-groups (lanes kg = bits [0:3))
    acc += __shfl_xor_sync(0xFFFFFFFFu, acc, 1);
    acc += __shfl_xor_sync(0xFFFFFFFFu, acc, 2);
    acc += __shfl_xor_sync(0xFFFFFFFFu, acc, 4);

    if (kg == 0 && tq < 30) {
        // weights: 2 for 0<k<450, 1 for k=0 and k=450
        float corr = S[0].x + ((t & 1) ? -S[450].x : S[450].x);
        out[b * W_ + t] = (2.f * acc - corr) * (1.f / 900.f);
    }
}

extern "C" void kernel_launch(void* const* d_in, const int* in_sizes, int n_in,
                              void* d_out, int out_size) {
    const float* x1 = (const float*)d_in[0];
    const float* x2 = (const float*)d_in[1];
    float* out = (float*)d_out;

    cudaFuncSetAttribute(fft_kernel,
                         cudaFuncAttributeMaxDynamicSharedMemorySize, SMEM_BYTES);

    twiddle_kernel<<<4, 256>>>(0);
    fft_kernel<<<2048, 256, SMEM_BYTES>>>(x1, x2);
    reduce_spec_kernel<<<(B_ * 451 + 255) / 256, 256>>>(0);
    idft_kernel<<<dim3(B_, 30), 256>>>(out);
}

// round 17
// speedup vs baseline: 1.1699x; 1.1699x over previous
#include <cuda_runtime.h>
#include <cstdint>

// out[b,t] = sum_w <x1[b,:,(t+w+450)%900,:], x2[b,:,w,:]>
// Spectral: per channel, circular cross-correlation via one packed FFT-900.
//   z = x1 + i*x2;  X1 = (Z(k)+conj(Z(-k)))/2,  X2 = (Z(k)-conj(Z(-k)))/(2i)
//   S[k] = sum_ch (-1)^k X1(k) conj(X2(k));  out[t] = (1/900) Re sum_k S[k] e^{+2pi i k t/900}
// FFT-900 = 30x30 CT, DFT-30 = 5x6 CT (hardcoded W5/W6 -> FFMA-imm).
// R17: transpose stages PACKED complex channel-major (coalesced fft loads,
// the R13-proven fast path), R13 fft compute shape, parallel final stages.

#define W_ 900
#define B_ 16

__device__ float2 g_z[16384 * W_];        // packed (x1,x2) channel-major
__device__ float2 g_W900[W_];             // e^{-2 pi i j / 900}
__device__ float2 g_spart[2048 * 452];    // per-(b,chgroup) partial spectra
__device__ float2 g_S[B_ * 452];          // reduced spectra per batch

// fft smem layout (float2 units): zw 8*962 | W 904 | Pall 8*452
#define ZW_STRIDE 962
#define WSH_OFF   7696
#define PALL_OFF  8600
#define SMEM_F2   12216
#define SMEM_BYTES (SMEM_F2 * 8)          // 97728

// ---------------- small-DFT constants (e^{-2 pi i j / N}) ----------------
__device__ constexpr float W6re[6] = { 1.f,  0.5f, -0.5f, -1.f, -0.5f,  0.5f };
__device__ constexpr float W6im[6] = { 0.f, -0.86602540378f, -0.86602540378f, 0.f,
                                       0.86602540378f,  0.86602540378f };
__device__ constexpr float W5re[5] = { 1.f,  0.30901699437f, -0.80901699437f,
                                      -0.80901699437f,  0.30901699437f };
__device__ constexpr float W5im[5] = { 0.f, -0.95105651630f, -0.58778525229f,
                                       0.58778525229f,  0.95105651630f };

__device__ __forceinline__ float2 cmul(float2 a, float2 b) {
    return make_float2(a.x * b.x - a.y * b.y, a.x * b.y + a.y * b.x);
}

// DFT-30 (natural in/out), 30 = 5 x 6. MODE 0: row pass + W900^{lane*q},
// swizzled row store. MODE 1: column pass, final Z layout.
template <int MODE>
__device__ __forceinline__ void dft30_io(float2* v, float2* zw,
                                         const float2* Wsh, int lane) {
#pragma unroll
    for (int m1 = 0; m1 < 5; ++m1) {
        float2 e[6];
#pragma unroll
        for (int m2 = 0; m2 < 6; ++m2) e[m2] = v[m1 + 5 * m2];
#pragma unroll
        for (int q2 = 0; q2 < 6; ++q2) {
            float re = 0.f, im = 0.f;
#pragma unroll
            for (int m2 = 0; m2 < 6; ++m2) {
                const float wr = W6re[(m2 * q2) % 6];
                const float wi = W6im[(m2 * q2) % 6];
                re += e[m2].x * wr - e[m2].y * wi;
                im += e[m2].x * wi + e[m2].y * wr;
            }
            float2 t = make_float2(re, im);
            if (m1 * q2 != 0) t = cmul(t, Wsh[30 * m1 * q2]);  // W30^{m1 q2}
            v[m1 + 5 * q2] = t;
        }
    }
#pragma unroll
    for (int q2 = 0; q2 < 6; ++q2) {
        float2 f[5];
#pragma unroll
        for (int m1 = 0; m1 < 5; ++m1) f[m1] = v[m1 + 5 * q2];
#pragma unroll
        for (int q1 = 0; q1 < 5; ++q1) {
            float re = 0.f, im = 0.f;
#pragma unroll
            for (int m1 = 0; m1 < 5; ++m1) {
                const float wr = W5re[(m1 * q1) % 5];
                const float wi = W5im[(m1 * q1) % 5];
                re += f[m1].x * wr - f[m1].y * wi;
                im += f[m1].x * wi + f[m1].y * wr;
            }
            const int q = q2 + 6 * q1;
            float2 o = make_float2(re, im);
            if (MODE == 0) {
                o = cmul(o, Wsh[lane * q]);              // W900^{r q}
                zw[lane * 32 + ((q + lane) & 31)] = o;
            } else {
                zw[q * 32 + ((lane + q) & 31)] = o;
            }
        }
    }
}

// ---------------- kernel 1: transpose to packed channel-major -----------
// grid (29, 8, 64): w-tile, c-tile, bh. Writes g_z[ch][w] = (x1, x2).
__global__ __launch_bounds__(256)
void transpose_kernel(const float* __restrict__ x1, const float* __restrict__ x2) {
    __shared__ float t1[32][33];
    __shared__ float t2[32][33];
    const int tx = threadIdx.x, ty = threadIdx.y;
    const int bh = blockIdx.z;
    const float* s1 = x1 + (size_t)bh * W_ * 256;
    const float* s2 = x2 + (size_t)bh * W_ * 256;
    const int w0 = blockIdx.x * 32, c0 = blockIdx.y * 32;

#pragma unroll
    for (int i = 0; i < 4; ++i) {
        int w = w0 + ty + i * 8;
        if (w < W_) {
            t1[ty + i * 8][tx] = s1[(size_t)w * 256 + c0 + tx];
            t2[ty + i * 8][tx] = s2[(size_t)w * 256 + c0 + tx];
        }
    }
    __syncthreads();
    const int wt = w0 + tx;
#pragma unroll
    for (int i = 0; i < 4; ++i) {
        int ct = c0 + ty + i * 8;
        if (wt < W_)
            g_z[(size_t)(bh * 256 + ct) * W_ + wt] =
                make_float2(t1[tx][ty + i * 8], t2[tx][ty + i * 8]);
    }

    if (blockIdx.x == 0 && blockIdx.y == 0 && blockIdx.z == 0) {
        int tid = ty * 32 + tx;
        for (int j = tid; j < W_; j += 256) {
            double s, c;
            sincospi(-2.0 * (double)j / 900.0, &s, &c);
            g_W900[j] = make_float2((float)c, (float)s);
        }
    }
}

__global__ void dummy_kernel(int unused) {}

// ---------------- kernel 2: FFT + cross-spectrum + CTA partial ----------
// grid 2048; 8 warps; warp wid owns channel bx*8 + wid (coalesced float2).
__global__ __launch_bounds__(256)
void fft_kernel(int unused) {
    extern __shared__ float2 sm[];
    float2* Wsh  = sm + WSH_OFF;
    float2* Pall = sm + PALL_OFF;

    const int tid  = threadIdx.x;
    const int lane = tid & 31;
    const int wid  = tid >> 5;
    const int bx   = blockIdx.x;
    const int ch   = bx * 8 + wid;

    for (int j = tid; j < W_; j += 256) Wsh[j] = g_W900[j];

    float2* zw = sm + wid * ZW_STRIDE;
    float2* Pb = Pall + wid * 452;

    // coalesced packed load: one float2 stream per warp
    const float2* p = g_z + (size_t)ch * W_;
    for (int idx = lane; idx < W_; idx += 32) {
        int r = idx % 30, cc = idx / 30;
        zw[r * 32 + ((cc + r) & 31)] = p[idx];
    }
    __syncthreads();   // also covers Wsh fill

    // stage 1: DFT-30 along rows + level-1 twiddle
    if (lane < 30) {
        float2 v[30];
#pragma unroll
        for (int c = 0; c < 30; ++c) v[c] = zw[lane * 32 + ((c + lane) & 31)];
        dft30_io<0>(v, zw, Wsh, lane);
    }
    __syncwarp();

    // stage 2: DFT-30 along columns
    if (lane < 30) {
        float2 v[30];
#pragma unroll
        for (int m = 0; m < 30; ++m) v[m] = zw[m * 32 + ((lane + m) & 31)];
        dft30_io<1>(v, zw, Wsh, lane);
    }
    __syncwarp();

    // combine: P[k] = (-1)^k X1(k) conj(X2(k)), k = 0..450 -> smem
    for (int k = lane; k <= 450; k += 32) {
        int m = (W_ - k) % W_;
        float2 A  = zw[(k / 30) * 32 + ((k % 30 + k / 30) & 31)];
        float2 Zm = zw[(m / 30) * 32 + ((m % 30 + m / 30) & 31)];
        float2 X1 = make_float2(0.5f * (A.x + Zm.x), 0.5f * (A.y - Zm.y));
        float2 D  = make_float2(0.5f * (A.x - Zm.x), 0.5f * (A.y + Zm.y));
        float pr = X1.x * D.y - X1.y * D.x;
        float pi = X1.x * D.x + X1.y * D.y;
        float sg = (k & 1) ? -1.f : 1.f;
        Pb[k] = make_float2(sg * pr, sg * pi);
    }
    __syncthreads();

    // CTA-reduce 8 warps -> partial spectrum for this channel group
    float2* part = g_spart + (size_t)bx * 452;
    for (int k = tid; k <= 450; k += 256) {
        float2 s = make_float2(0.f, 0.f);
#pragma unroll
        for (int w = 0; w < 8; ++w) {
            float2 q = Pall[w * 452 + k];
            s.x += q.x; s.y += q.y;
        }
        part[k] = s;
    }
}

// ---------------- kernel 3: reduce 128 partials -> S[b][k] --------------
__global__ __launch_bounds__(256)
void reduce_spec_kernel(int unused) {
    const int idx = blockIdx.x * 256 + threadIdx.x;
    if (idx >= B_ * 451) return;
    const int b = idx / 451;
    const int k = idx - b * 451;
    float2 s = make_float2(0.f, 0.f);
#pragma unroll 8
    for (int g = 0; g < 128; ++g) {
        float2 p = g_spart[(size_t)(b * 128 + g) * 452 + k];
        s.x += p.x; s.y += p.y;
    }
    g_S[b * 452 + k] = s;
}

// ---------------- kernel 4: parallel inverse real DFT -------------------
// grid (16, 30); thread = (t_local of 30, kgroup of 8); dual accumulators.
__global__ __launch_bounds__(256)
void idft_kernel(float* __restrict__ out) {
    __shared__ float2 S[452];
    __shared__ float2 Wsh[W_];
    const int tid = threadIdx.x;
    const int b = blockIdx.x;

    for (int j = tid; j < W_; j += 256) Wsh[j] = g_W900[j];
    for (int k = tid; k <= 450; k += 256) S[k] = g_S[b * 452 + k];
    __syncthreads();

    const int tq = tid >> 3;            // 0..31 (valid outputs: < 30)
    const int kg = tid & 7;
    const int traw = blockIdx.y * 30 + tq;
    const int t = (tq < 30) ? traw : 0; // clamp dead lanes (bounds safety)
    const int k0 = kg * 57;
    const int k1 = (k0 + 56 < 450) ? (k0 + 56) : 450;

    const int dt2 = (2 * t) % W_;
    float acc0 = 0.f, acc1 = 0.f;
    int idx0 = (k0 * t) % W_;
    int idx1 = idx0 + t; if (idx1 >= W_) idx1 -= W_;
    for (int k = k0; k <= k1; k += 2) {
        float2 Wa = Wsh[idx0];
        float2 sa = S[k];
        acc0 += sa.x * Wa.x + sa.y * Wa.y;
        idx0 += dt2; if (idx0 >= W_) idx0 -= W_;
        if (k + 1 <= k1) {
            float2 Wb = Wsh[idx1];
            float2 sb = S[k + 1];
            acc1 += sb.x * Wb.x + sb.y * Wb.y;
            idx1 += dt2; if (idx1 >= W_) idx1 -= W_;
        }
    }
    float acc = acc0 + acc1;
    acc += __shfl_xor_sync(0xFFFFFFFFu, acc, 1);
    acc += __shfl_xor_sync(0xFFFFFFFFu, acc, 2);
    acc += __shfl_xor_sync(0xFFFFFFFFu, acc, 4);

    if (kg == 0 && tq < 30) {
        // weights: 2 for 0<k<450, 1 for k=0 and k=450
        float corr = S[0].x + ((t & 1) ? -S[450].x : S[450].x);
        out[b * W_ + t] = (2.f * acc - corr) * (1.f / 900.f);
    }
}

extern "C" void kernel_launch(void* const* d_in, const int* in_sizes, int n_in,
                              void* d_out, int out_size) {
    const float* x1 = (const float*)d_in[0];
    const float* x2 = (const float*)d_in[1];
    float* out = (float*)d_out;

    cudaFuncSetAttribute(fft_kernel,
                         cudaFuncAttributeMaxDynamicSharedMemorySize, SMEM_BYTES);

    // Sequence position 3 = ncu's flat launch idx 5 -> profiles fft_kernel.
    transpose_kernel<<<dim3(29, 8, 64), dim3(32, 8)>>>(x1, x2);
    dummy_kernel<<<1, 32>>>(0);
    dummy_kernel<<<1, 32>>>(0);
    fft_kernel<<<2048, 256, SMEM_BYTES>>>(0);
    reduce_spec_kernel<<<(B_ * 451 + 255) / 256, 256>>>(0);
    idft_kernel<<<dim3(B_, 30), 256>>>(out);
}